// round 3
// baseline (speedup 1.0000x reference)
#include <cuda_runtime.h>
#include <float.h>

#define BB 4
#define DD 64
#define NN 4096
#define KNN 16
#define SPLIT 4
#define TQ 128
#define NCAND (NN / SPLIT) /* 1024 */
#define CC 32

#define EF_ELEMS ((size_t)BB * 2 * DD * NN * KNN) /* 33,554,432 */

// Scratch (allocation-free rule: __device__ globals)
__device__ float g_sqn[BB * NN];
__device__ float g_pdist[BB * SPLIT * NN * KNN];
__device__ int   g_pidx[BB * SPLIT * NN * KNN];
__device__ int   g_fidx[BB * NN * KNN];

// ---------------------------------------------------------------------------
// Kernel 1: squared norms. The reference's transpose is fused into the
// reduction, so the reduce axis (d) is strided -> XLA column-reduce pattern:
// ONE sequential fp32 FMA chain over d ascending per output point.
// (CPU backend vectorizes over n with d sequential per lane: same chain.)
// ---------------------------------------------------------------------------
__global__ void sqnorm_kernel(const float* __restrict__ pc) {
    int t = blockIdx.x * blockDim.x + threadIdx.x;
    if (t >= BB * NN) return;
    int b = t / NN, n = t % NN;
    const float* p = pc + (size_t)b * DD * NN + n;
    float s = 0.f;
#pragma unroll
    for (int d = 0; d < DD; ++d) {
        float v = p[(size_t)d * NN];
        s = __fmaf_rn(v, v, s);
    }
    g_sqn[t] = s;
}

// ---------------------------------------------------------------------------
// Stable insertion into sorted (dist asc, index asc) top-16 list.
// Equal keys go AFTER existing entries (lower candidate index first, since
// candidates are processed in ascending index order) == jax stable top_k.
// ---------------------------------------------------------------------------
__device__ __forceinline__ void insert16(float* bestd, int* besti, float dd, int ii) {
    if (dd < bestd[KNN - 1]) {
        bool placed = false;
#pragma unroll
        for (int j = KNN - 1; j >= 1; --j) {
            if (!placed) {
                if (dd < bestd[j - 1]) {
                    bestd[j] = bestd[j - 1];
                    besti[j] = besti[j - 1];
                } else {
                    bestd[j] = dd;
                    besti[j] = ii;
                    placed = true;
                }
            }
        }
        if (!placed) { bestd[0] = dd; besti[0] = ii; }
    }
}

// ---------------------------------------------------------------------------
// Kernel 2: partial kNN. Query per thread (regs), candidates staged in smem.
// Dot product is a STRICT sequential fp32 FMA chain (k ascending, acc = 0),
// emulating cuBLAS SGEMM / Eigen gebp per-output accumulation.
// Key = fp32 sqrt(max(sq_q + sq_c - 2*dot, 0)) — the reference's exact value.
// ---------------------------------------------------------------------------
__global__ void __launch_bounds__(TQ) knn_partial(const float* __restrict__ pc) {
    const int qt = blockIdx.x;
    const int b  = blockIdx.y;
    const int sp = blockIdx.z;
    const int q  = qt * TQ + threadIdx.x;

    const float* pcb = pc + (size_t)b * DD * NN;

    float qv[DD];
#pragma unroll
    for (int d = 0; d < DD; ++d) qv[d] = pcb[(size_t)d * NN + q];
    const float sqq = g_sqn[b * NN + q];

    float bestd[KNN];
    int   besti[KNN];
#pragma unroll
    for (int k = 0; k < KNN; ++k) { bestd[k] = FLT_MAX; besti[k] = -1; }

    __shared__ float sc[CC * DD];   // [cand][dim], 16B-aligned rows
    __shared__ float ssq[CC];

    const int c0base = sp * NCAND;

    for (int cc0 = 0; cc0 < NCAND; cc0 += CC) {
        const int c0 = c0base + cc0;
        __syncthreads();
        for (int i = threadIdx.x; i < CC * DD; i += TQ) {
            int d = i / CC;
            int c = i % CC;
            sc[c * DD + d] = pcb[(size_t)d * NN + c0 + c];
        }
        if (threadIdx.x < CC) ssq[threadIdx.x] = g_sqn[b * NN + c0 + threadIdx.x];
        __syncthreads();

#pragma unroll 1
        for (int c = 0; c < CC; c += 2) {
            const float4* r0 = (const float4*)&sc[c * DD];
            const float4* r1 = (const float4*)&sc[(c + 1) * DD];
            float a0 = 0.f, a1 = 0.f;   // two independent sequential chains
#pragma unroll
            for (int j = 0; j < DD / 4; ++j) {
                float4 x = r0[j];
                float4 y = r1[j];
                a0 = __fmaf_rn(qv[4 * j + 0], x.x, a0);
                a0 = __fmaf_rn(qv[4 * j + 1], x.y, a0);
                a0 = __fmaf_rn(qv[4 * j + 2], x.z, a0);
                a0 = __fmaf_rn(qv[4 * j + 3], x.w, a0);
                a1 = __fmaf_rn(qv[4 * j + 0], y.x, a1);
                a1 = __fmaf_rn(qv[4 * j + 1], y.y, a1);
                a1 = __fmaf_rn(qv[4 * j + 2], y.z, a1);
                a1 = __fmaf_rn(qv[4 * j + 3], y.w, a1);
            }
            float d20 = __fsub_rn(__fadd_rn(sqq, ssq[c]),     __fmul_rn(2.0f, a0));
            float d21 = __fsub_rn(__fadd_rn(sqq, ssq[c + 1]), __fmul_rn(2.0f, a1));
            float di0 = __fsqrt_rn(fmaxf(d20, 0.0f));
            float di1 = __fsqrt_rn(fmaxf(d21, 0.0f));
            int ci0 = c0 + c, ci1 = c0 + c + 1;
            if (ci0 != q) insert16(bestd, besti, di0, ci0);
            if (ci1 != q) insert16(bestd, besti, di1, ci1);
        }
    }

    const size_t off = (((size_t)b * SPLIT + sp) * NN + q) * KNN;
#pragma unroll
    for (int k = 0; k < KNN; ++k) {
        g_pdist[off + k] = bestd[k];
        g_pidx[off + k]  = besti[k];
    }
}

// ---------------------------------------------------------------------------
// Kernel 3: merge SPLIT partial sorted lists -> final top-16, index-stable.
// Scan order (split asc, rank asc) == candidate-index order for equal keys.
// ---------------------------------------------------------------------------
__global__ void knn_merge(float* __restrict__ out_idx) {
    int t = blockIdx.x * blockDim.x + threadIdx.x;
    if (t >= BB * NN) return;
    int b = t / NN, n = t % NN;

    float dloc[SPLIT * KNN];
    int   iloc[SPLIT * KNN];
#pragma unroll
    for (int s = 0; s < SPLIT; ++s) {
        size_t off = (((size_t)b * SPLIT + s) * NN + n) * KNN;
#pragma unroll
        for (int k = 0; k < KNN; ++k) {
            dloc[s * KNN + k] = g_pdist[off + k];
            iloc[s * KNN + k] = g_pidx[off + k];
        }
    }
    size_t obase = (size_t)t * KNN;
    for (int k = 0; k < KNN; ++k) {
        float bd = dloc[0];
        int   bp = 0;
        for (int j = 1; j < SPLIT * KNN; ++j) {
            if (dloc[j] < bd) { bd = dloc[j]; bp = j; }
        }
        int bi = iloc[bp];
        dloc[bp] = FLT_MAX;
        g_fidx[obase + k]  = bi;
        out_idx[obase + k] = (float)bi;
    }
}

// ---------------------------------------------------------------------------
// Kernel 4: edge feature writer.
// ef[b, d,      n, k] = pc[b, d, n]
// ef[b, 64 + d, n, k] = pc[b, d, idx[b,n,k]] - pc[b, d, n]
// ---------------------------------------------------------------------------
__global__ void edge_kernel(const float* __restrict__ pc, float* __restrict__ out) {
    int t = blockIdx.x * blockDim.x + threadIdx.x;
    if (t >= BB * DD * NN) return;
    int n  = t % NN;
    int bd = t / NN;
    int d  = bd % DD;
    int b  = bd / DD;

    const float* row = pc + ((size_t)b * DD + d) * NN;
    float cen = row[n];

    const int* id = &g_fidx[((size_t)b * NN + n) * KNN];
    float nb[KNN];
#pragma unroll
    for (int k = 0; k < KNN; ++k) nb[k] = row[id[k]] - cen;

    size_t o1 = (((size_t)b * 2 * DD + d) * NN + n) * KNN;
    size_t o2 = (((size_t)b * 2 * DD + DD + d) * NN + n) * KNN;

    float4  cv = make_float4(cen, cen, cen, cen);
    float4* p1 = (float4*)(out + o1);
    p1[0] = cv; p1[1] = cv; p1[2] = cv; p1[3] = cv;

    float4* p2 = (float4*)(out + o2);
    p2[0] = make_float4(nb[0],  nb[1],  nb[2],  nb[3]);
    p2[1] = make_float4(nb[4],  nb[5],  nb[6],  nb[7]);
    p2[2] = make_float4(nb[8],  nb[9],  nb[10], nb[11]);
    p2[3] = make_float4(nb[12], nb[13], nb[14], nb[15]);
}

// ---------------------------------------------------------------------------
extern "C" void kernel_launch(void* const* d_in, const int* in_sizes, int n_in,
                              void* d_out, int out_size) {
    const float* pc = (const float*)d_in[0];
    float* out = (float*)d_out;

    sqnorm_kernel<<<(BB * NN + 255) / 256, 256>>>(pc);

    dim3 grid(NN / TQ, BB, SPLIT);
    knn_partial<<<grid, TQ>>>(pc);

    knn_merge<<<(BB * NN + 255) / 256, 256>>>(out + EF_ELEMS);

    edge_kernel<<<(BB * DD * NN + 255) / 256, 256>>>(pc, out);
}